// round 12
// baseline (speedup 1.0000x reference)
#include <cuda_runtime.h>
#include <cuda_bf16.h>
#include <cstdint>
#include <math.h>

// Problem dims (fixed by dataset)
#define TSTEPS 16
#define NNODES 4096
#define RDIM   256
#define CDIM   32

// Scratch (static device globals — no allocation)
__device__ float g_Mz[RDIM * RDIM];                       // Wz + Uz (row-major)
__device__ float g_Mr[RDIM * RDIM];                       // Wr + Ur (row-major)
__device__ float g_q [CDIM * RDIM];                       // q  in [c][k] layout
__device__ float g_rq[CDIM * RDIM];                       // rq in [c][k] layout
__device__ unsigned g_bar_cnt;                            // grid-sync arrivals (0 at rest)
__device__ unsigned g_bar_gen;                            // grid-sync generation
__device__ unsigned short g_Qth[TSTEPS * CDIM * RDIM];    // Q^T hi bf16 [t][n][k]
__device__ unsigned short g_Qtl[TSTEPS * CDIM * RDIM];    // Q^T lo bf16
__device__ unsigned short g_Yth[TSTEPS * CDIM * NNODES];  // Y^T hi bf16 [t][n][k]
__device__ unsigned short g_Ytl[TSTEPS * CDIM * NNODES];  // Y^T lo bf16

// ---------------------------------------------------------------------------
// Small PTX helpers
// ---------------------------------------------------------------------------
__device__ __forceinline__ uint32_t smem_u32(const void* p) {
    uint32_t a;
    asm("{ .reg .u64 t; cvta.to.shared.u64 t, %1; cvt.u32.u64 %0, t; }"
        : "=r"(a) : "l"(p));
    return a;
}
__device__ __forceinline__ uint32_t cvt_bf16x2(float hi, float lo) {
    uint32_t r;
    asm("cvt.rn.bf16x2.f32 %0, %1, %2;" : "=r"(r) : "f"(hi), "f"(lo));
    return r;
}
__device__ __forceinline__ void ldsm4(uint32_t* r, uint32_t a) {
    asm volatile("ldmatrix.sync.aligned.m8n8.x4.shared.b16 {%0,%1,%2,%3}, [%4];"
                 : "=r"(r[0]), "=r"(r[1]), "=r"(r[2]), "=r"(r[3]) : "r"(a));
}
__device__ __forceinline__ void mma16816(float* c, const uint32_t* a,
                                         uint32_t b0, uint32_t b1) {
    asm volatile(
        "mma.sync.aligned.m16n8k16.row.col.f32.bf16.bf16.f32 "
        "{%0,%1,%2,%3}, {%4,%5,%6,%7}, {%8,%9}, {%0,%1,%2,%3};"
        : "+f"(c[0]), "+f"(c[1]), "+f"(c[2]), "+f"(c[3])
        : "r"(a[0]), "r"(a[1]), "r"(a[2]), "r"(a[3]), "r"(b0), "r"(b1));
}
__device__ __forceinline__ float2 ldsf2(uint32_t a) {
    float2 v;
    asm volatile("ld.shared.v2.f32 {%0,%1}, [%2];" : "=f"(v.x), "=f"(v.y) : "r"(a));
    return v;
}
__device__ __forceinline__ void cpasync16(uint32_t s, const void* g) {
    asm volatile("cp.async.cg.shared.global [%0], [%1], 16;" :: "r"(s), "l"(g));
}
__device__ __forceinline__ void cp_commit() {
    asm volatile("cp.async.commit_group;" ::: "memory");
}
// Split fp32 pair -> bf16x2 hi (lower=f.x) + bf16x2 residual lo
__device__ __forceinline__ void split2(float2 f, uint32_t& h, uint32_t& l) {
    h = cvt_bf16x2(f.y, f.x);
    float gx = __uint_as_float(h << 16);
    float gy = __uint_as_float(h & 0xFFFF0000u);
    l = cvt_bf16x2(f.y - gy, f.x - gx);
}
__device__ __forceinline__ float dot4(float4 a, float4 b) {
    return a.x * b.x + a.y * b.y + a.z * b.z + a.w * b.w;
}

// ---------------------------------------------------------------------------
// Prep: fold z/r gate weight pairs (W@Q + U@Q = (W+U)@Q), row-major out.
// ---------------------------------------------------------------------------
__global__ void prep_fold(const float* __restrict__ Wz, const float* __restrict__ Uz,
                          const float* __restrict__ Wr, const float* __restrict__ Ur) {
    int i = blockIdx.x * blockDim.x + threadIdx.x;
    g_Mz[i] = Wz[i] + Uz[i];
    g_Mr[i] = Wr[i] + Ur[i];
}

// ---------------------------------------------------------------------------
// Software grid barrier: 32 blocks, all guaranteed resident.
// ---------------------------------------------------------------------------
#define GRU_NB 32
__device__ __forceinline__ void gsync() {
    __syncthreads();
    if (threadIdx.x == 0) {
        __threadfence();
        unsigned gen = *(volatile unsigned*)&g_bar_gen;
        if (atomicAdd(&g_bar_cnt, 1u) == GRU_NB - 1) {
            g_bar_cnt = 0;
            __threadfence();
            atomicAdd(&g_bar_gen, 1u);
        } else {
            while (*(volatile unsigned*)&g_bar_gen == gen) { }
        }
        __threadfence();
    }
    __syncthreads();
}

// ---------------------------------------------------------------------------
// GRU evolution of Q [256,32] over 16 steps — persistent weights-in-smem.
// (Measured-good in R11; unchanged.)
// ---------------------------------------------------------------------------
#define QP 260
#define GRU_SMEM ((4 * 8 * 256 + 2 * 32 * QP) * 4)   // 99328 B

__global__ void __launch_bounds__(256, 1) gru_persist(const float* __restrict__ Q0,
                                                      const float* __restrict__ Whg,
                                                      const float* __restrict__ Uhg) {
    extern __shared__ float sm[];
    float* wz = sm;            // [8][256]
    float* wr = sm + 2048;
    float* wh = sm + 4096;
    float* uh = sm + 6144;
    float* qs = sm + 8192;     // [32][QP]
    float* rs = sm + 8192 + 32 * QP;

    const int tid = threadIdx.x;
    const int w = tid >> 5, c = tid & 31;
    const int r0 = blockIdx.x * 8;

    #pragma unroll
    for (int i = 0; i < 2; i++) {
        int idx = tid + i * 256;
        int row = idx >> 6, j = (idx & 63) * 4;
        long src = (long)(r0 + row) * RDIM + j;
        *(float4*)&wz[row * 256 + j] = *(const float4*)&g_Mz[src];
        *(float4*)&wr[row * 256 + j] = *(const float4*)&g_Mr[src];
        *(float4*)&wh[row * 256 + j] = *(const float4*)&Whg[src];
        *(float4*)&uh[row * 256 + j] = *(const float4*)&Uhg[src];
    }
    g_q[c * RDIM + r0 + w] = Q0[(r0 + w) * CDIM + c];
    __threadfence();
    gsync();

    for (int t = 0; t < TSTEPS; t++) {
        #pragma unroll
        for (int i = 0; i < 8; i++) {
            int idx = tid + i * 256;
            int cc = idx >> 6, j = (idx & 63) * 4;
            *(float4*)&qs[cc * QP + j] = *(const float4*)&g_q[cc * RDIM + j];
        }
        __syncthreads();

        float sz = 0.f, sr = 0.f;
        #pragma unroll 4
        for (int k4 = 0; k4 < 64; k4++) {
            float4 a  = *(const float4*)&wz[w * 256 + k4 * 4];
            float4 d  = *(const float4*)&wr[w * 256 + k4 * 4];
            float4 bq = *(const float4*)&qs[c * QP + k4 * 4];
            sz += dot4(a, bq);
            sr += dot4(d, bq);
        }
        float z    = 1.f / (1.f + expf(-sz));
        float rg   = 1.f / (1.f + expf(-sr));
        float qown = qs[c * QP + r0 + w];
        g_rq[c * RDIM + r0 + w] = rg * qown;
        __threadfence();
        gsync();

        #pragma unroll
        for (int i = 0; i < 8; i++) {
            int idx = tid + i * 256;
            int cc = idx >> 6, j = (idx & 63) * 4;
            *(float4*)&rs[cc * QP + j] = *(const float4*)&g_rq[cc * RDIM + j];
        }
        __syncthreads();

        float sh = 0.f;
        #pragma unroll 4
        for (int k4 = 0; k4 < 64; k4++) {
            float4 a  = *(const float4*)&wh[w * 256 + k4 * 4];
            float4 d  = *(const float4*)&uh[w * 256 + k4 * 4];
            float4 bq = *(const float4*)&qs[c * QP + k4 * 4];
            float4 e  = *(const float4*)&rs[c * QP + k4 * 4];
            sh += dot4(a, bq) + dot4(d, e);
        }
        float h  = tanhf(sh);
        float qn = (1.f - z) * qown + z * h;
        g_q[c * RDIM + r0 + w] = qn;

        uint32_t ph = cvt_bf16x2(0.f, qn);
        float    hf = __uint_as_float(ph << 16);
        uint32_t pl = cvt_bf16x2(0.f, qn - hf);
        long qoff = ((long)t * CDIM + c) * RDIM + r0 + w;
        g_Qth[qoff] = (unsigned short)(ph & 0xFFFFu);
        g_Qtl[qoff] = (unsigned short)(pl & 0xFFFFu);
        __threadfence();
        gsync();
    }
}

// ---------------------------------------------------------------------------
// Unified tensor GEMM: D[128m x 32n] = A[t] @ B[t]^T, 3-stage cp.async.
//   K consumed in 32-wide chunks (CH=32), NSTG=3 stages -> wait_group 2 gives
//   two chunks of load slack; 3 CTAs/SM (70.6 KB smem each).
//   A: fp32, converted to bf16 hi/lo at fragment-load time from smem.
//   B: bf16 hi/lo via ldmatrix (pitch 40 ushorts: 8 ldsm rows hit 8 distinct
//      bank-quads -> conflict-free).
//   3 split-precision terms: Ah*Bh + Ah*Bl + Al*Bh.
// TRANS_OUT=false: Out[t][m][n] = relu(D)      (AY, NC=128)
// TRANS_OUT=true : OutT hi/lo [t][n][m] bf16   (XQ, NC=8)
// ---------------------------------------------------------------------------
#define CH   32                             // K per chunk
#define NSTG 3
#define AFP  36                             // fp32 word pitch (32 + 4 pad)
#define BPD  40                             // bf16 pitch (32 + 8 pad)
#define ASTG (128 * AFP * 4)                // 18432 B
#define BSTG (32 * BPD * 2)                 // 2560 B
#define OFF_A(s)  ((s) * ASTG)
#define OFF_BH(s) (NSTG * ASTG + (s) * BSTG)
#define OFF_BL(s) (NSTG * ASTG + NSTG * BSTG + (s) * BSTG)
#define SMEM_BYTES (NSTG * ASTG + 2 * NSTG * BSTG)   // 70656 B

template<int NC, bool TRANS_OUT>
__global__ void __launch_bounds__(128, 3) mma_gemm(
    const float* __restrict__ Abase,
    const unsigned short* __restrict__ Bhb,
    const unsigned short* __restrict__ Blb,
    float* __restrict__ Out,
    unsigned short* __restrict__ OTh,
    unsigned short* __restrict__ OTl) {

    constexpr int K = NC * CH;
    extern __shared__ __align__(16) unsigned char smem[];
    const uint32_t sb = smem_u32(smem);

    const int tid  = threadIdx.x;
    const int wid  = tid >> 5;
    const int lane = tid & 31;
    const int t    = blockIdx.y;
    const int mb   = blockIdx.x;

    const float* Ap = Abase + ((long)t * NNODES + (long)mb * 128) * K;
    const unsigned short* Bgh = Bhb + (long)t * CDIM * K;
    const unsigned short* Bgl = Blb + (long)t * CDIM * K;

    // ldmatrix B lane offsets (byte)
    const int g = lane >> 3;
    const int rowB = (lane & 7) + ((g >> 1) ? 8 : 0);
    const uint32_t offB0 = rowB * (BPD * 2) + (g & 1) * 16;
    const uint32_t offB1 = offB0 + 16 * (BPD * 2);

    // A fragment lane offsets (fp32 smem)
    const int g4 = lane >> 2;
    const int t2 = (lane & 3) * 2;

    float acc[2][4][4];
    #pragma unroll
    for (int ti = 0; ti < 2; ti++)
        #pragma unroll
        for (int j = 0; j < 4; j++)
            #pragma unroll
            for (int i = 0; i < 4; i++) acc[ti][j][i] = 0.f;

    // cp.async one chunk (A: 1024 float4 -> 8/thread; B hi+lo: 1 line each/thread)
    auto load_async = [&](int c, int s) {
        const float* ap = Ap + c * CH;
        #pragma unroll
        for (int i = 0; i < 8; i++) {
            int idx = tid + i * 128;
            int m = idx >> 3, j = idx & 7;
            cpasync16(sb + OFF_A(s) + (m * AFP + j * 4) * 4,
                      ap + (long)m * K + j * 4);
        }
        {
            int n = tid >> 2, jj = tid & 3;
            long go = (long)n * K + c * CH + jj * 8;
            uint32_t so = (n * BPD + jj * 8) * 2;
            cpasync16(sb + OFF_BH(s) + so, Bgh + go);
            cpasync16(sb + OFF_BL(s) + so, Bgl + go);
        }
        cp_commit();
    };

    auto compute = [&](int s) {
        const uint32_t aBase = sb + OFF_A(s);
        const uint32_t bhB   = sb + OFF_BH(s);
        const uint32_t blB   = sb + OFF_BL(s);
        #pragma unroll
        for (int ks = 0; ks < 2; ks++) {
            uint32_t bh[8], bl[8];
            ldsm4(bh,     bhB + offB0 + ks * 32);
            ldsm4(bh + 4, bhB + offB1 + ks * 32);
            ldsm4(bl,     blB + offB0 + ks * 32);
            ldsm4(bl + 4, blB + offB1 + ks * 32);
            #pragma unroll
            for (int ti = 0; ti < 2; ti++) {
                uint32_t pa = aBase + (((wid * 32 + ti * 16 + g4) * AFP) + ks * 16 + t2) * 4;
                float2 x0 = ldsf2(pa);
                float2 x1 = ldsf2(pa + 8 * AFP * 4);
                float2 x2 = ldsf2(pa + 32);
                float2 x3 = ldsf2(pa + 8 * AFP * 4 + 32);
                uint32_t ah[4], al[4];
                split2(x0, ah[0], al[0]);
                split2(x1, ah[1], al[1]);
                split2(x2, ah[2], al[2]);
                split2(x3, ah[3], al[3]);
                #pragma unroll
                for (int j = 0; j < 4; j++) {
                    mma16816(acc[ti][j], ah, bh[2 * j], bh[2 * j + 1]);
                    mma16816(acc[ti][j], ah, bl[2 * j], bl[2 * j + 1]);
                    mma16816(acc[ti][j], al, bh[2 * j], bh[2 * j + 1]);
                }
            }
        }
    };

    // Prologue: fill NSTG-1 stages
    load_async(0, 0);
    if (NC > 1) load_async(1, 1);

    for (int c = 0; c < NC; c++) {
        int s = c % NSTG;
        if (c + 2 < NC) {
            load_async(c + 2, (c + 2) % NSTG);
            asm volatile("cp.async.wait_group 2;" ::: "memory");
        } else if (c + 1 < NC) {
            asm volatile("cp.async.wait_group 1;" ::: "memory");
        } else {
            asm volatile("cp.async.wait_group 0;" ::: "memory");
        }
        __syncthreads();
        compute(s);
        __syncthreads();
    }

    const int cg = lane >> 2;
    const int tc = (lane & 3) * 2;

    if (!TRANS_OUT) {
        // relu + direct store [t][m][n]
        #pragma unroll
        for (int ti = 0; ti < 2; ti++) {
            const long row0 = (long)t * NNODES + mb * 128 + wid * 32 + ti * 16 + cg;
            #pragma unroll
            for (int j = 0; j < 4; j++) {
                float2 v0, v1;
                v0.x = fmaxf(acc[ti][j][0], 0.f);
                v0.y = fmaxf(acc[ti][j][1], 0.f);
                v1.x = fmaxf(acc[ti][j][2], 0.f);
                v1.y = fmaxf(acc[ti][j][3], 0.f);
                *(float2*)(Out + row0 * CDIM + j * 8 + tc)       = v0;
                *(float2*)(Out + (row0 + 8) * CDIM + j * 8 + tc) = v1;
            }
        }
    } else {
        // Transpose through smem, split bf16 hi/lo, store [t][n][m]
        float* S = (float*)smem;     // [32][132] fp32 (smem reused)
        #pragma unroll
        for (int ti = 0; ti < 2; ti++) {
            int m = wid * 32 + ti * 16 + cg;
            #pragma unroll
            for (int j = 0; j < 4; j++) {
                int n = j * 8 + tc;
                S[n * 132 + m]           = acc[ti][j][0];
                S[(n + 1) * 132 + m]     = acc[ti][j][1];
                S[n * 132 + m + 8]       = acc[ti][j][2];
                S[(n + 1) * 132 + m + 8] = acc[ti][j][3];
            }
        }
        __syncthreads();
        const int n  = tid >> 2;
        const int ms = (tid & 3) * 32;
        float v[32];
        #pragma unroll
        for (int i = 0; i < 8; i++)
            *(float4*)&v[i * 4] = *(const float4*)&S[n * 132 + ms + i * 4];
        uint32_t hp[16], lp[16];
        #pragma unroll
        for (int i = 0; i < 16; i++) {
            hp[i] = cvt_bf16x2(v[2 * i + 1], v[2 * i]);
            float g0 = __uint_as_float(hp[i] << 16);
            float g1 = __uint_as_float(hp[i] & 0xFFFF0000u);
            lp[i] = cvt_bf16x2(v[2 * i + 1] - g1, v[2 * i] - g0);
        }
        long ooff = ((long)t * CDIM + n) * NNODES + mb * 128 + ms;  // ushort units
        #pragma unroll
        for (int i = 0; i < 4; i++) {
            *(uint4*)(OTh + ooff + i * 8) =
                make_uint4(hp[4 * i], hp[4 * i + 1], hp[4 * i + 2], hp[4 * i + 3]);
            *(uint4*)(OTl + ooff + i * 8) =
                make_uint4(lp[4 * i], lp[4 * i + 1], lp[4 * i + 2], lp[4 * i + 3]);
        }
    }
}

// ---------------------------------------------------------------------------
// Launch: prep_fold -> GRU (persistent) -> XQ (NC=8) -> AY (NC=128)
// ---------------------------------------------------------------------------
extern "C" void kernel_launch(void* const* d_in, const int* in_sizes, int n_in,
                              void* d_out, int out_size) {
    const float* A  = (const float*)d_in[0];   // [1,16,4096,4096]
    const float* X  = (const float*)d_in[1];   // [16,4096,256]
    const float* Q0 = (const float*)d_in[2];   // [256,32]
    const float* Wz = (const float*)d_in[3];
    const float* Uz = (const float*)d_in[4];
    const float* Wr = (const float*)d_in[5];
    const float* Ur = (const float*)d_in[6];
    const float* Wh = (const float*)d_in[7];
    const float* Uh = (const float*)d_in[8];
    float* out = (float*)d_out;                // [16,4096,32]

    void *pQh = nullptr, *pQl = nullptr, *pYh = nullptr, *pYl = nullptr;
    cudaGetSymbolAddress(&pQh, g_Qth);
    cudaGetSymbolAddress(&pQl, g_Qtl);
    cudaGetSymbolAddress(&pYh, g_Yth);
    cudaGetSymbolAddress(&pYl, g_Ytl);

    cudaFuncSetAttribute(gru_persist,
                         cudaFuncAttributeMaxDynamicSharedMemorySize, GRU_SMEM);
    cudaFuncSetAttribute(mma_gemm<8, true>,
                         cudaFuncAttributeMaxDynamicSharedMemorySize, SMEM_BYTES);
    cudaFuncSetAttribute(mma_gemm<128, false>,
                         cudaFuncAttributeMaxDynamicSharedMemorySize, SMEM_BYTES);

    // 1. Fold z/r gate weights
    prep_fold<<<RDIM * RDIM / 256, 256>>>(Wz, Uz, Wr, Ur);

    // 2. Evolve Q over 16 steps (32 persistent blocks, weights loaded once)
    gru_persist<<<GRU_NB, 256, GRU_SMEM>>>(Q0, Wh, Uh);

    // 3. Y_t = X_t @ Q_t -> Y^T bf16 hi/lo
    mma_gemm<8, true><<<dim3(NNODES / 128, TSTEPS), 128, SMEM_BYTES>>>(
        X, (const unsigned short*)pQh, (const unsigned short*)pQl,
        nullptr, (unsigned short*)pYh, (unsigned short*)pYl);

    // 4. out_t = relu(A_t @ Y_t)
    mma_gemm<128, false><<<dim3(NNODES / 128, TSTEPS), 128, SMEM_BYTES>>>(
        A, (const unsigned short*)pYh, (const unsigned short*)pYl,
        out, nullptr, nullptr);
}

// round 13
// speedup vs baseline: 1.5908x; 1.5908x over previous
#include <cuda_runtime.h>
#include <cuda_bf16.h>
#include <cstdint>
#include <math.h>

// Problem dims (fixed by dataset)
#define TSTEPS 16
#define NNODES 4096
#define RDIM   256
#define CDIM   32

// Scratch (static device globals — no allocation)
__device__ float g_Mz[RDIM * RDIM];                       // Wz + Uz (row-major)
__device__ float g_Mr[RDIM * RDIM];                       // Wr + Ur (row-major)
__device__ float g_q [CDIM * RDIM];                       // q  in [c][k] layout
__device__ float g_rq[CDIM * RDIM];                       // rq in [c][k] layout
__device__ unsigned g_bar_cnt;                            // grid-sync arrivals (0 at rest)
__device__ unsigned g_bar_gen;                            // grid-sync generation
__device__ unsigned short g_Qth[TSTEPS * CDIM * RDIM];    // Q^T hi bf16 [t][n][k]
__device__ unsigned short g_Qtl[TSTEPS * CDIM * RDIM];    // Q^T lo bf16
__device__ unsigned short g_Yth[TSTEPS * CDIM * NNODES];  // Y^T hi bf16 [t][n][k]
__device__ unsigned short g_Ytl[TSTEPS * CDIM * NNODES];  // Y^T lo bf16

// ---------------------------------------------------------------------------
// Small PTX helpers
// ---------------------------------------------------------------------------
__device__ __forceinline__ uint32_t smem_u32(const void* p) {
    uint32_t a;
    asm("{ .reg .u64 t; cvta.to.shared.u64 t, %1; cvt.u32.u64 %0, t; }"
        : "=r"(a) : "l"(p));
    return a;
}
__device__ __forceinline__ uint32_t cvt_bf16x2(float hi, float lo) {
    uint32_t r;
    asm("cvt.rn.bf16x2.f32 %0, %1, %2;" : "=r"(r) : "f"(hi), "f"(lo));
    return r;
}
__device__ __forceinline__ void ldsm4(uint32_t* r, uint32_t a) {
    asm volatile("ldmatrix.sync.aligned.m8n8.x4.shared.b16 {%0,%1,%2,%3}, [%4];"
                 : "=r"(r[0]), "=r"(r[1]), "=r"(r[2]), "=r"(r[3]) : "r"(a));
}
__device__ __forceinline__ void mma16816(float* c, const uint32_t* a,
                                         uint32_t b0, uint32_t b1) {
    asm volatile(
        "mma.sync.aligned.m16n8k16.row.col.f32.bf16.bf16.f32 "
        "{%0,%1,%2,%3}, {%4,%5,%6,%7}, {%8,%9}, {%0,%1,%2,%3};"
        : "+f"(c[0]), "+f"(c[1]), "+f"(c[2]), "+f"(c[3])
        : "r"(a[0]), "r"(a[1]), "r"(a[2]), "r"(a[3]), "r"(b0), "r"(b1));
}
__device__ __forceinline__ float2 ldsf2(uint32_t a) {
    float2 v;
    asm volatile("ld.shared.v2.f32 {%0,%1}, [%2];" : "=f"(v.x), "=f"(v.y) : "r"(a));
    return v;
}
__device__ __forceinline__ void cpasync16(uint32_t s, const void* g) {
    asm volatile("cp.async.cg.shared.global [%0], [%1], 16;" :: "r"(s), "l"(g));
}
__device__ __forceinline__ void cp_commit() {
    asm volatile("cp.async.commit_group;" ::: "memory");
}
// Split fp32 pair -> bf16x2 hi (lower=f.x) + bf16x2 residual lo
__device__ __forceinline__ void split2(float2 f, uint32_t& h, uint32_t& l) {
    h = cvt_bf16x2(f.y, f.x);
    float gx = __uint_as_float(h << 16);
    float gy = __uint_as_float(h & 0xFFFF0000u);
    l = cvt_bf16x2(f.y - gy, f.x - gx);
}
__device__ __forceinline__ float dot4(float4 a, float4 b) {
    return a.x * b.x + a.y * b.y + a.z * b.z + a.w * b.w;
}

// ---------------------------------------------------------------------------
// Prep: fold z/r gate weight pairs (W@Q + U@Q = (W+U)@Q), row-major out.
// ---------------------------------------------------------------------------
__global__ void prep_fold(const float* __restrict__ Wz, const float* __restrict__ Uz,
                          const float* __restrict__ Wr, const float* __restrict__ Ur) {
    int i = blockIdx.x * blockDim.x + threadIdx.x;
    g_Mz[i] = Wz[i] + Uz[i];
    g_Mr[i] = Wr[i] + Ur[i];
}

// ---------------------------------------------------------------------------
// Software grid barrier: 32 blocks, all guaranteed resident.
// ---------------------------------------------------------------------------
#define GRU_NB 32
__device__ __forceinline__ void gsync() {
    __syncthreads();
    if (threadIdx.x == 0) {
        __threadfence();
        unsigned gen = *(volatile unsigned*)&g_bar_gen;
        if (atomicAdd(&g_bar_cnt, 1u) == GRU_NB - 1) {
            g_bar_cnt = 0;
            __threadfence();
            atomicAdd(&g_bar_gen, 1u);
        } else {
            while (*(volatile unsigned*)&g_bar_gen == gen) { }
        }
        __threadfence();
    }
    __syncthreads();
}

// ---------------------------------------------------------------------------
// GRU evolution of Q [256,32] over 16 steps — persistent weights-in-smem.
// (Measured-good in R11; unchanged.)
// ---------------------------------------------------------------------------
#define QP 260
#define GRU_SMEM ((4 * 8 * 256 + 2 * 32 * QP) * 4)   // 99328 B

__global__ void __launch_bounds__(256, 1) gru_persist(const float* __restrict__ Q0,
                                                      const float* __restrict__ Whg,
                                                      const float* __restrict__ Uhg) {
    extern __shared__ float sm[];
    float* wz = sm;            // [8][256]
    float* wr = sm + 2048;
    float* wh = sm + 4096;
    float* uh = sm + 6144;
    float* qs = sm + 8192;     // [32][QP]
    float* rs = sm + 8192 + 32 * QP;

    const int tid = threadIdx.x;
    const int w = tid >> 5, c = tid & 31;
    const int r0 = blockIdx.x * 8;

    #pragma unroll
    for (int i = 0; i < 2; i++) {
        int idx = tid + i * 256;
        int row = idx >> 6, j = (idx & 63) * 4;
        long src = (long)(r0 + row) * RDIM + j;
        *(float4*)&wz[row * 256 + j] = *(const float4*)&g_Mz[src];
        *(float4*)&wr[row * 256 + j] = *(const float4*)&g_Mr[src];
        *(float4*)&wh[row * 256 + j] = *(const float4*)&Whg[src];
        *(float4*)&uh[row * 256 + j] = *(const float4*)&Uhg[src];
    }
    g_q[c * RDIM + r0 + w] = Q0[(r0 + w) * CDIM + c];
    __threadfence();
    gsync();

    for (int t = 0; t < TSTEPS; t++) {
        #pragma unroll
        for (int i = 0; i < 8; i++) {
            int idx = tid + i * 256;
            int cc = idx >> 6, j = (idx & 63) * 4;
            *(float4*)&qs[cc * QP + j] = *(const float4*)&g_q[cc * RDIM + j];
        }
        __syncthreads();

        float sz = 0.f, sr = 0.f;
        #pragma unroll 4
        for (int k4 = 0; k4 < 64; k4++) {
            float4 a  = *(const float4*)&wz[w * 256 + k4 * 4];
            float4 d  = *(const float4*)&wr[w * 256 + k4 * 4];
            float4 bq = *(const float4*)&qs[c * QP + k4 * 4];
            sz += dot4(a, bq);
            sr += dot4(d, bq);
        }
        float z    = 1.f / (1.f + expf(-sz));
        float rg   = 1.f / (1.f + expf(-sr));
        float qown = qs[c * QP + r0 + w];
        g_rq[c * RDIM + r0 + w] = rg * qown;
        __threadfence();
        gsync();

        #pragma unroll
        for (int i = 0; i < 8; i++) {
            int idx = tid + i * 256;
            int cc = idx >> 6, j = (idx & 63) * 4;
            *(float4*)&rs[cc * QP + j] = *(const float4*)&g_rq[cc * RDIM + j];
        }
        __syncthreads();

        float sh = 0.f;
        #pragma unroll 4
        for (int k4 = 0; k4 < 64; k4++) {
            float4 a  = *(const float4*)&wh[w * 256 + k4 * 4];
            float4 d  = *(const float4*)&uh[w * 256 + k4 * 4];
            float4 bq = *(const float4*)&qs[c * QP + k4 * 4];
            float4 e  = *(const float4*)&rs[c * QP + k4 * 4];
            sh += dot4(a, bq) + dot4(d, e);
        }
        float h  = tanhf(sh);
        float qn = (1.f - z) * qown + z * h;
        g_q[c * RDIM + r0 + w] = qn;

        uint32_t ph = cvt_bf16x2(0.f, qn);
        float    hf = __uint_as_float(ph << 16);
        uint32_t pl = cvt_bf16x2(0.f, qn - hf);
        long qoff = ((long)t * CDIM + c) * RDIM + r0 + w;
        g_Qth[qoff] = (unsigned short)(ph & 0xFFFFu);
        g_Qtl[qoff] = (unsigned short)(pl & 0xFFFFu);
        __threadfence();
        gsync();
    }
}

// ---------------------------------------------------------------------------
// XQ: Y_t = X_t @ Q_t (static-smem register-staged kernel; part of the
// measured 422us R11 build — unchanged).
// ---------------------------------------------------------------------------
#define APAD 72
#define SM_AH 0
#define SM_AL (128 * APAD * 2)
#define SM_BH (2 * 128 * APAD * 2)
#define SM_BL (2 * 128 * APAD * 2 + 32 * APAD * 2)
#define SM_TOT (2 * 128 * APAD * 2 + 2 * 32 * APAD * 2)

__global__ void __launch_bounds__(128, 3) xq_mma(
    const float* __restrict__ Abase,
    const unsigned short* __restrict__ Bhb,
    const unsigned short* __restrict__ Blb,
    unsigned short* __restrict__ OTh,
    unsigned short* __restrict__ OTl) {

    constexpr int NC = 4;
    constexpr int K  = NC * 64;   // 256
    __shared__ __align__(16) unsigned char smem[SM_TOT];

    const int tid  = threadIdx.x;
    const int wid  = tid >> 5;
    const int lane = tid & 31;
    const int t    = blockIdx.y;
    const int mb   = blockIdx.x;

    const float* Ap = Abase + ((long)t * NNODES + (long)mb * 128) * K;
    const unsigned short* Bgh = Bhb + (long)t * CDIM * K;
    const unsigned short* Bgl = Blb + (long)t * CDIM * K;

    int aoff[16];
    int smA[16];   // byte offsets
    #pragma unroll
    for (int i = 0; i < 16; i++) {
        int idx = tid + i * 128;
        int m = idx >> 4, qd = idx & 15;
        aoff[i] = m * K + qd * 4;
        smA[i]  = (m * APAD + qd * 4) * 2;
    }
    int boffB[2], smB[2];
    #pragma unroll
    for (int i = 0; i < 2; i++) {
        int idx = tid + i * 128;
        int bn = idx >> 3, bq = idx & 7;
        boffB[i] = bn * K + bq * 8;     // ushort units
        smB[i]   = (bn * APAD + bq * 8) * 2;
    }

    const uint32_t sb = smem_u32(smem);
    const int g = lane >> 3;
    const int rowA = wid * 32 + (lane & 7) + ((g & 1) ? 8 : 0);
    const uint32_t offA0 = rowA * (APAD * 2) + (g >> 1) * 16;
    const uint32_t offA1 = offA0 + 16 * (APAD * 2);
    const int rowB = (lane & 7) + ((g >> 1) ? 8 : 0);
    const uint32_t offB0 = rowB * (APAD * 2) + (g & 1) * 16;
    const uint32_t offB1 = offB0 + 16 * (APAD * 2);

    float acc[2][4][4];
    #pragma unroll
    for (int ti = 0; ti < 2; ti++)
        #pragma unroll
        for (int j = 0; j < 4; j++)
            #pragma unroll
            for (int i = 0; i < 4; i++) acc[ti][j][i] = 0.f;

    float4 aR[16];
    uint4  bhR[2], blR[2];

    auto fetch = [&](int c) {
        const float* ap = Ap + c * 64;
        #pragma unroll
        for (int i = 0; i < 16; i++) aR[i] = *(const float4*)(ap + aoff[i]);
        #pragma unroll
        for (int i = 0; i < 2; i++) {
            bhR[i] = *(const uint4*)(Bgh + boffB[i] + c * 64);
            blR[i] = *(const uint4*)(Bgl + boffB[i] + c * 64);
        }
    };
    auto stage = [&]() {
        #pragma unroll
        for (int i = 0; i < 16; i++) {
            float4 f = aR[i];
            uint32_t h01 = cvt_bf16x2(f.y, f.x);
            uint32_t h23 = cvt_bf16x2(f.w, f.z);
            float g0 = __uint_as_float(h01 << 16);
            float g1 = __uint_as_float(h01 & 0xFFFF0000u);
            float g2 = __uint_as_float(h23 << 16);
            float g3 = __uint_as_float(h23 & 0xFFFF0000u);
            uint32_t l01 = cvt_bf16x2(f.y - g1, f.x - g0);
            uint32_t l23 = cvt_bf16x2(f.w - g3, f.z - g2);
            *(uint2*)(smem + SM_AH + smA[i]) = make_uint2(h01, h23);
            *(uint2*)(smem + SM_AL + smA[i]) = make_uint2(l01, l23);
        }
        #pragma unroll
        for (int i = 0; i < 2; i++) {
            *(uint4*)(smem + SM_BH + smB[i]) = bhR[i];
            *(uint4*)(smem + SM_BL + smB[i]) = blR[i];
        }
    };

    fetch(0);
    stage();
    __syncthreads();

    for (int c = 0; c < NC; c++) {
        if (c + 1 < NC) fetch(c + 1);

        #pragma unroll
        for (int ks = 0; ks < 4; ks++) {
            uint32_t ah0[4], al0[4], ah1[4], al1[4], bh[8], bl[8];
            ldsm4(ah0, sb + SM_AH + offA0 + ks * 32);
            ldsm4(ah1, sb + SM_AH + offA1 + ks * 32);
            ldsm4(al0, sb + SM_AL + offA0 + ks * 32);
            ldsm4(al1, sb + SM_AL + offA1 + ks * 32);
            ldsm4(bh,     sb + SM_BH + offB0 + ks * 32);
            ldsm4(bh + 4, sb + SM_BH + offB1 + ks * 32);
            ldsm4(bl,     sb + SM_BL + offB0 + ks * 32);
            ldsm4(bl + 4, sb + SM_BL + offB1 + ks * 32);
            #pragma unroll
            for (int j = 0; j < 4; j++) {
                mma16816(acc[0][j], ah0, bh[2 * j], bh[2 * j + 1]);
                mma16816(acc[0][j], ah0, bl[2 * j], bl[2 * j + 1]);
                mma16816(acc[0][j], al0, bh[2 * j], bh[2 * j + 1]);
                mma16816(acc[1][j], ah1, bh[2 * j], bh[2 * j + 1]);
                mma16816(acc[1][j], ah1, bl[2 * j], bl[2 * j + 1]);
                mma16816(acc[1][j], al1, bh[2 * j], bh[2 * j + 1]);
            }
        }
        __syncthreads();
        if (c + 1 < NC) {
            stage();
            __syncthreads();
        }
    }

    // Epilogue: transpose through smem, split bf16 hi/lo, store [t][n][m]
    const int cg = lane >> 2;
    const int tc = (lane & 3) * 2;
    float* S = (float*)smem;     // [32][132] fp32 (smem reused)
    #pragma unroll
    for (int ti = 0; ti < 2; ti++) {
        int m = wid * 32 + ti * 16 + cg;
        #pragma unroll
        for (int j = 0; j < 4; j++) {
            int n = j * 8 + tc;
            S[n * 132 + m]           = acc[ti][j][0];
            S[(n + 1) * 132 + m]     = acc[ti][j][1];
            S[n * 132 + m + 8]       = acc[ti][j][2];
            S[(n + 1) * 132 + m + 8] = acc[ti][j][3];
        }
    }
    __syncthreads();
    const int n  = tid >> 2;
    const int ms = (tid & 3) * 32;
    float v[32];
    #pragma unroll
    for (int i = 0; i < 8; i++)
        *(float4*)&v[i * 4] = *(const float4*)&S[n * 132 + ms + i * 4];
    uint32_t hp[16], lp[16];
    #pragma unroll
    for (int i = 0; i < 16; i++) {
        hp[i] = cvt_bf16x2(v[2 * i + 1], v[2 * i]);
        float g0 = __uint_as_float(hp[i] << 16);
        float g1 = __uint_as_float(hp[i] & 0xFFFF0000u);
        lp[i] = cvt_bf16x2(v[2 * i + 1] - g1, v[2 * i] - g0);
    }
    long ooff = ((long)t * CDIM + n) * NNODES + mb * 128 + ms;  // ushort units
    #pragma unroll
    for (int i = 0; i < 4; i++) {
        *(uint4*)(OTh + ooff + i * 8) =
            make_uint4(hp[4 * i], hp[4 * i + 1], hp[4 * i + 2], hp[4 * i + 3]);
        *(uint4*)(OTl + ooff + i * 8) =
            make_uint4(lp[4 * i], lp[4 * i + 1], lp[4 * i + 2], lp[4 * i + 3]);
    }
}

// ---------------------------------------------------------------------------
// AY: out_t = relu(A_t @ Y_t) — cp.async CH=64 2-stage (measured layout),
// now with 256 threads = 8 warps x one m16 tile each (2x warps/SM for
// latency hiding; B-frag reads duplicated but L1 has headroom).
// ---------------------------------------------------------------------------
#define AFP 72                              // fp32 pitch for A smem
#define BPD 72                              // bf16 pitch for B smem
#define ASTG (128 * AFP * 4)                // 36864 B per A stage
#define BSTG (32 * BPD * 2)                 // 4608 B per B stage
#define OFF_A(s)  ((s) * ASTG)
#define OFF_BH(s) (2 * ASTG + (s) * BSTG)
#define OFF_BL(s) (2 * ASTG + 2 * BSTG + (s) * BSTG)
#define SMEM_BYTES (2 * ASTG + 4 * BSTG)    // 92160 B

__global__ void __launch_bounds__(256, 2) ay_mma(
    const float* __restrict__ Abase,
    const unsigned short* __restrict__ Bhb,
    const unsigned short* __restrict__ Blb,
    float* __restrict__ Out) {

    constexpr int NC = 64;
    constexpr int K  = NC * 64;   // 4096
    extern __shared__ __align__(16) unsigned char smem[];
    const uint32_t sb = smem_u32(smem);

    const int tid  = threadIdx.x;
    const int wid  = tid >> 5;         // 0..7, warp owns rows wid*16..+15
    const int lane = tid & 31;
    const int t    = blockIdx.y;
    const int mb   = blockIdx.x;

    const float* Ap = Abase + ((long)t * NNODES + (long)mb * 128) * K;
    const unsigned short* Bgh = Bhb + (long)t * CDIM * K;
    const unsigned short* Bgl = Blb + (long)t * CDIM * K;

    // ldmatrix B lane offsets (byte)
    const int g = lane >> 3;
    const int rowB = (lane & 7) + ((g >> 1) ? 8 : 0);
    const uint32_t offB0 = rowB * (BPD * 2) + (g & 1) * 16;
    const uint32_t offB1 = offB0 + 16 * (BPD * 2);

    // A fragment lane offsets (fp32 smem)
    const int g4 = lane >> 2;
    const int t2 = (lane & 3) * 2;

    float acc[4][4];
    #pragma unroll
    for (int j = 0; j < 4; j++)
        #pragma unroll
        for (int i = 0; i < 4; i++) acc[j][i] = 0.f;

    auto load_async = [&](int c, int s) {
        const float* ap = Ap + c * 64;
        // A: 128 rows x 64 fp32 = 2048 float4; 8 per thread
        #pragma unroll
        for (int i = 0; i < 8; i++) {
            int idx = tid + i * 256;
            int m = idx >> 4, j = idx & 15;
            cpasync16(sb + OFF_A(s) + (m * AFP + j * 4) * 4,
                      ap + (long)m * K + j * 4);
        }
        // B hi/lo: 32 rows x 64 bf16 = 256 lines each; 1 per thread each
        {
            int n = tid >> 3, jj = tid & 7;
            long go = (long)n * K + c * 64 + jj * 8;
            uint32_t so = (n * BPD + jj * 8) * 2;
            cpasync16(sb + OFF_BH(s) + so, Bgh + go);
            cpasync16(sb + OFF_BL(s) + so, Bgl + go);
        }
        cp_commit();
    };

    auto compute = [&](int s) {
        const uint32_t aBase = sb + OFF_A(s);
        const uint32_t bhB   = sb + OFF_BH(s);
        const uint32_t blB   = sb + OFF_BL(s);
        #pragma unroll
        for (int ks = 0; ks < 4; ks++) {
            uint32_t bh[8], bl[8];
            ldsm4(bh,     bhB + offB0 + ks * 32);
            ldsm4(bh + 4, bhB + offB1 + ks * 32);
            ldsm4(bl,     blB + offB0 + ks * 32);
            ldsm4(bl + 4, blB + offB1 + ks * 32);
            uint32_t pa = aBase + (((wid * 16 + g4) * AFP) + ks * 16 + t2) * 4;
            float2 x0 = ldsf2(pa);
            float2 x1 = ldsf2(pa + 8 * AFP * 4);
            float2 x2 = ldsf2(pa + 32);
            float2 x3 = ldsf2(pa + 8 * AFP * 4 + 32);
            uint32_t ah[4], al[4];
            split2(x0, ah[0], al[0]);
            split2(x1, ah[1], al[1]);
            split2(x2, ah[2], al[2]);
            split2(x3, ah[3], al[3]);
            #pragma unroll
            for (int j = 0; j < 4; j++) {
                mma16816(acc[j], ah, bh[2 * j], bh[2 * j + 1]);
                mma16816(acc[j], ah, bl[2 * j], bl[2 * j + 1]);
                mma16816(acc[j], al, bh[2 * j], bh[2 * j + 1]);
            }
        }
    };

    load_async(0, 0);
    for (int c = 0; c < NC; c++) {
        int buf = c & 1;
        if (c + 1 < NC) {
            load_async(c + 1, buf ^ 1);
            asm volatile("cp.async.wait_group 1;" ::: "memory");
        } else {
            asm volatile("cp.async.wait_group 0;" ::: "memory");
        }
        __syncthreads();
        compute(buf);
        __syncthreads();
    }

    // Epilogue: relu + direct store [t][m][n]
    const int cg = lane >> 2;
    const int tc = (lane & 3) * 2;
    const long row0 = (long)t * NNODES + mb * 128 + wid * 16 + cg;
    #pragma unroll
    for (int j = 0; j < 4; j++) {
        float2 v0, v1;
        v0.x = fmaxf(acc[j][0], 0.f);
        v0.y = fmaxf(acc[j][1], 0.f);
        v1.x = fmaxf(acc[j][2], 0.f);
        v1.y = fmaxf(acc[j][3], 0.f);
        *(float2*)(Out + row0 * CDIM + j * 8 + tc)       = v0;
        *(float2*)(Out + (row0 + 8) * CDIM + j * 8 + tc) = v1;
    }
}

// ---------------------------------------------------------------------------
// Launch: prep_fold -> GRU (persistent) -> XQ (static) -> AY (256-thread)
// ---------------------------------------------------------------------------
extern "C" void kernel_launch(void* const* d_in, const int* in_sizes, int n_in,
                              void* d_out, int out_size) {
    const float* A  = (const float*)d_in[0];   // [1,16,4096,4096]
    const float* X  = (const float*)d_in[1];   // [16,4096,256]
    const float* Q0 = (const float*)d_in[2];   // [256,32]
    const float* Wz = (const float*)d_in[3];
    const float* Uz = (const float*)d_in[4];
    const float* Wr = (const float*)d_in[5];
    const float* Ur = (const float*)d_in[6];
    const float* Wh = (const float*)d_in[7];
    const float* Uh = (const float*)d_in[8];
    float* out = (float*)d_out;                // [16,4096,32]

    void *pQh = nullptr, *pQl = nullptr, *pYh = nullptr, *pYl = nullptr;
    cudaGetSymbolAddress(&pQh, g_Qth);
    cudaGetSymbolAddress(&pQl, g_Qtl);
    cudaGetSymbolAddress(&pYh, g_Yth);
    cudaGetSymbolAddress(&pYl, g_Ytl);

    cudaFuncSetAttribute(gru_persist,
                         cudaFuncAttributeMaxDynamicSharedMemorySize, GRU_SMEM);
    cudaFuncSetAttribute(ay_mma,
                         cudaFuncAttributeMaxDynamicSharedMemorySize, SMEM_BYTES);

    // 1. Fold z/r gate weights
    prep_fold<<<RDIM * RDIM / 256, 256>>>(Wz, Uz, Wr, Ur);

    // 2. Evolve Q over 16 steps (32 persistent blocks, weights loaded once)
    gru_persist<<<GRU_NB, 256, GRU_SMEM>>>(Q0, Wh, Uh);

    // 3. Y_t = X_t @ Q_t (static-smem tensor kernel) -> Y^T bf16 hi/lo
    xq_mma<<<dim3(NNODES / 128, TSTEPS), 128>>>(
        X, (const unsigned short*)pQh, (const unsigned short*)pQl,
        (unsigned short*)pYh, (unsigned short*)pYl);

    // 4. out_t = relu(A_t @ Y_t) (cp.async, 8 warps)
    ay_mma<<<dim3(NNODES / 128, TSTEPS), 256, SMEM_BYTES>>>(
        A, (const unsigned short*)pYh, (const unsigned short*)pYl, out);
}

// round 16
// speedup vs baseline: 1.6086x; 1.0112x over previous
#include <cuda_runtime.h>
#include <cuda_bf16.h>
#include <cstdint>
#include <math.h>

// Problem dims (fixed by dataset)
#define TSTEPS 16
#define NNODES 4096
#define RDIM   256
#define CDIM   32

// Scratch (static device globals — no allocation)
// q / rq live in the interleaved layout: flat[((r>>2)*32 + c)*4 + (r&3)]
// i.e. [k4][c] float4 groups — conflict-free lane-major smem reads.
__device__ float g_q [CDIM * RDIM];
__device__ float g_rq[CDIM * RDIM];
__device__ unsigned g_bar_cnt;                            // grid-sync arrivals (0 at rest)
__device__ unsigned g_bar_gen;                            // grid-sync generation
__device__ unsigned short g_Qth[TSTEPS * CDIM * RDIM];    // Q^T hi bf16 [t][n][k]
__device__ unsigned short g_Qtl[TSTEPS * CDIM * RDIM];    // Q^T lo bf16
__device__ unsigned short g_Yth[TSTEPS * CDIM * NNODES];  // Y^T hi bf16 [t][n][k]
__device__ unsigned short g_Ytl[TSTEPS * CDIM * NNODES];  // Y^T lo bf16

// ---------------------------------------------------------------------------
// Small PTX helpers
// ---------------------------------------------------------------------------
__device__ __forceinline__ uint32_t smem_u32(const void* p) {
    uint32_t a;
    asm("{ .reg .u64 t; cvta.to.shared.u64 t, %1; cvt.u32.u64 %0, t; }"
        : "=r"(a) : "l"(p));
    return a;
}
__device__ __forceinline__ uint32_t cvt_bf16x2(float hi, float lo) {
    uint32_t r;
    asm("cvt.rn.bf16x2.f32 %0, %1, %2;" : "=r"(r) : "f"(hi), "f"(lo));
    return r;
}
__device__ __forceinline__ void ldsm4(uint32_t* r, uint32_t a) {
    asm volatile("ldmatrix.sync.aligned.m8n8.x4.shared.b16 {%0,%1,%2,%3}, [%4];"
                 : "=r"(r[0]), "=r"(r[1]), "=r"(r[2]), "=r"(r[3]) : "r"(a));
}
__device__ __forceinline__ void mma16816(float* c, const uint32_t* a,
                                         uint32_t b0, uint32_t b1) {
    asm volatile(
        "mma.sync.aligned.m16n8k16.row.col.f32.bf16.bf16.f32 "
        "{%0,%1,%2,%3}, {%4,%5,%6,%7}, {%8,%9}, {%0,%1,%2,%3};"
        : "+f"(c[0]), "+f"(c[1]), "+f"(c[2]), "+f"(c[3])
        : "r"(a[0]), "r"(a[1]), "r"(a[2]), "r"(a[3]), "r"(b0), "r"(b1));
}
__device__ __forceinline__ float2 ldsf2(uint32_t a) {
    float2 v;
    asm volatile("ld.shared.v2.f32 {%0,%1}, [%2];" : "=f"(v.x), "=f"(v.y) : "r"(a));
    return v;
}
__device__ __forceinline__ void cpasync16(uint32_t s, const void* g) {
    asm volatile("cp.async.cg.shared.global [%0], [%1], 16;" :: "r"(s), "l"(g));
}
__device__ __forceinline__ void cp_commit() {
    asm volatile("cp.async.commit_group;" ::: "memory");
}
// Split fp32 pair -> bf16x2 hi (lower=f.x) + bf16x2 residual lo
__device__ __forceinline__ void split2(float2 f, uint32_t& h, uint32_t& l) {
    h = cvt_bf16x2(f.y, f.x);
    float gx = __uint_as_float(h << 16);
    float gy = __uint_as_float(h & 0xFFFF0000u);
    l = cvt_bf16x2(f.y - gy, f.x - gx);
}
// Packed fp32x2 FMA (Blackwell f32x2 pipe — 2 FMAs per issue)
__device__ __forceinline__ void ffma2(unsigned long long& d, unsigned long long a,
                                      unsigned long long b) {
    asm("fma.rn.f32x2 %0, %1, %2, %0;" : "+l"(d) : "l"(a), "l"(b));
}

// ---------------------------------------------------------------------------
// Software grid barrier: 32 blocks, all guaranteed resident.
// ---------------------------------------------------------------------------
#define GRU_NB 32
__device__ __forceinline__ void gsync() {
    __syncthreads();
    if (threadIdx.x == 0) {
        __threadfence();
        unsigned gen = *(volatile unsigned*)&g_bar_gen;
        if (atomicAdd(&g_bar_cnt, 1u) == GRU_NB - 1) {
            g_bar_cnt = 0;
            __threadfence();
            atomicAdd(&g_bar_gen, 1u);
        } else {
            while (*(volatile unsigned*)&g_bar_gen == gen) { }
        }
        __threadfence();
    }
    __syncthreads();
}

// ---------------------------------------------------------------------------
// GRU evolution of Q [256,32] over 16 steps — persistent weights-in-smem.
// Interleaved [k4][c] float4 q/rq layout (conflict-free lane reads, no
// transposes anywhere), packed f32x2 FMA accumulation, gate-fold done inline
// during the (one-time) weight load. 32 blocks x 256 threads; block owns 8
// rows of all 4 matrices; thread (w = row-local, c = column).
// ---------------------------------------------------------------------------
#define GRU_SMEM (24576 * 4)   // 96 KB: 4 x 8x256 weights + 2 x 8K q/rq

__global__ void __launch_bounds__(256, 1) gru_persist(
    const float* __restrict__ Q0,
    const float* __restrict__ Wzg, const float* __restrict__ Uzg,
    const float* __restrict__ Wrg, const float* __restrict__ Urg,
    const float* __restrict__ Whg, const float* __restrict__ Uhg) {
    extern __shared__ float sm[];
    float* wz = sm;            // [8][256]  (Wz+Uz folded)
    float* wr = sm + 2048;     // [8][256]  (Wr+Ur folded)
    float* wh = sm + 4096;
    float* uh = sm + 6144;
    float* qs = sm + 8192;     // interleaved [k4][c] float4 = 8192 floats
    float* rs = sm + 16384;

    const int tid = threadIdx.x;
    const int w = tid >> 5, c = tid & 31;
    const int r0 = blockIdx.x * 8;
    const int r  = r0 + w;                 // this thread's output row
    const int own = ((r >> 2) * 32 + c) * 4 + (r & 3);   // interleaved index

    // One-time: load this block's 8 rows of all matrices, folding gates.
    #pragma unroll
    for (int i = 0; i < 2; i++) {
        int idx = tid + i * 256;          // 512 float4 per matrix
        int row = idx >> 6, j = (idx & 63) * 4;
        long src = (long)(r0 + row) * RDIM + j;
        float4 a1 = *(const float4*)&Wzg[src];
        float4 a2 = *(const float4*)&Uzg[src];
        *(float4*)&wz[row * 256 + j] =
            make_float4(a1.x + a2.x, a1.y + a2.y, a1.z + a2.z, a1.w + a2.w);
        float4 b1 = *(const float4*)&Wrg[src];
        float4 b2 = *(const float4*)&Urg[src];
        *(float4*)&wr[row * 256 + j] =
            make_float4(b1.x + b2.x, b1.y + b2.y, b1.z + b2.z, b1.w + b2.w);
        *(float4*)&wh[row * 256 + j] = *(const float4*)&Whg[src];
        *(float4*)&uh[row * 256 + j] = *(const float4*)&Uhg[src];
    }
    // Init q (interleaved layout).
    g_q[own] = Q0[r * CDIM + c];
    __threadfence();
    gsync();

    for (int t = 0; t < TSTEPS; t++) {
        // Stage q (straight copy — same layout both sides)
        #pragma unroll
        for (int i = 0; i < 8; i++) {
            int idx = (tid + i * 256) * 4;
            *(float4*)&qs[idx] = *(const float4*)&g_q[idx];
        }
        __syncthreads();

        // Phase 1: gates via packed f32x2 dot products.
        unsigned long long sz2 = 0ull, sr2 = 0ull;
        #pragma unroll 8
        for (int k4 = 0; k4 < 64; k4++) {
            ulonglong2 wzv = *(const ulonglong2*)&wz[w * 256 + k4 * 4];
            ulonglong2 wrv = *(const ulonglong2*)&wr[w * 256 + k4 * 4];
            ulonglong2 qv  = *(const ulonglong2*)&qs[(k4 * 32 + c) * 4];
            ffma2(sz2, wzv.x, qv.x); ffma2(sz2, wzv.y, qv.y);
            ffma2(sr2, wrv.x, qv.x); ffma2(sr2, wrv.y, qv.y);
        }
        float2 szp = *(float2*)&sz2;
        float2 srp = *(float2*)&sr2;
        float sz = szp.x + szp.y;
        float sr = srp.x + srp.y;
        float z    = 1.f / (1.f + expf(-sz));
        float rg   = 1.f / (1.f + expf(-sr));
        float qown = qs[own];
        g_rq[own] = rg * qown;
        __threadfence();
        gsync();

        // Stage rq
        #pragma unroll
        for (int i = 0; i < 8; i++) {
            int idx = (tid + i * 256) * 4;
            *(float4*)&rs[idx] = *(const float4*)&g_rq[idx];
        }
        __syncthreads();

        // Phase 2: candidate.
        unsigned long long sh2 = 0ull;
        #pragma unroll 8
        for (int k4 = 0; k4 < 64; k4++) {
            ulonglong2 whv = *(const ulonglong2*)&wh[w * 256 + k4 * 4];
            ulonglong2 uhv = *(const ulonglong2*)&uh[w * 256 + k4 * 4];
            ulonglong2 qv  = *(const ulonglong2*)&qs[(k4 * 32 + c) * 4];
            ulonglong2 rv  = *(const ulonglong2*)&rs[(k4 * 32 + c) * 4];
            ffma2(sh2, whv.x, qv.x); ffma2(sh2, whv.y, qv.y);
            ffma2(sh2, uhv.x, rv.x); ffma2(sh2, uhv.y, rv.y);
        }
        float2 shp = *(float2*)&sh2;
        float sh = shp.x + shp.y;
        float h  = tanhf(sh);
        float qn = (1.f - z) * qown + z * h;
        g_q[own] = qn;

        // Emit Q^T bf16 hi/lo at [t][c][r]
        uint32_t ph = cvt_bf16x2(0.f, qn);
        float    hf = __uint_as_float(ph << 16);
        uint32_t pl = cvt_bf16x2(0.f, qn - hf);
        long qoff = ((long)t * CDIM + c) * RDIM + r;
        g_Qth[qoff] = (unsigned short)(ph & 0xFFFFu);
        g_Qtl[qoff] = (unsigned short)(pl & 0xFFFFu);
        __threadfence();
        gsync();
    }
}

// ---------------------------------------------------------------------------
// XQ: Y_t = X_t @ Q_t (static-smem register-staged kernel; measured-good,
// unchanged from the 420us build).
// ---------------------------------------------------------------------------
#define APAD 72
#define SM_AH 0
#define SM_AL (128 * APAD * 2)
#define SM_BH (2 * 128 * APAD * 2)
#define SM_BL (2 * 128 * APAD * 2 + 32 * APAD * 2)
#define SM_TOT (2 * 128 * APAD * 2 + 2 * 32 * APAD * 2)

__global__ void __launch_bounds__(128, 3) xq_mma(
    const float* __restrict__ Abase,
    const unsigned short* __restrict__ Bhb,
    const unsigned short* __restrict__ Blb,
    unsigned short* __restrict__ OTh,
    unsigned short* __restrict__ OTl) {

    constexpr int NC = 4;
    constexpr int K  = NC * 64;   // 256
    __shared__ __align__(16) unsigned char smem[SM_TOT];

    const int tid  = threadIdx.x;
    const int wid  = tid >> 5;
    const int lane = tid & 31;
    const int t    = blockIdx.y;
    const int mb   = blockIdx.x;

    const float* Ap = Abase + ((long)t * NNODES + (long)mb * 128) * K;
    const unsigned short* Bgh = Bhb + (long)t * CDIM * K;
    const unsigned short* Bgl = Blb + (long)t * CDIM * K;

    int aoff[16];
    int smA[16];   // byte offsets
    #pragma unroll
    for (int i = 0; i < 16; i++) {
        int idx = tid + i * 128;
        int m = idx >> 4, qd = idx & 15;
        aoff[i] = m * K + qd * 4;
        smA[i]  = (m * APAD + qd * 4) * 2;
    }
    int boffB[2], smB[2];
    #pragma unroll
    for (int i = 0; i < 2; i++) {
        int idx = tid + i * 128;
        int bn = idx >> 3, bq = idx & 7;
        boffB[i] = bn * K + bq * 8;     // ushort units
        smB[i]   = (bn * APAD + bq * 8) * 2;
    }

    const uint32_t sb = smem_u32(smem);
    const int g = lane >> 3;
    const int rowA = wid * 32 + (lane & 7) + ((g & 1) ? 8 : 0);
    const uint32_t offA0 = rowA * (APAD * 2) + (g >> 1) * 16;
    const uint32_t offA1 = offA0 + 16 * (APAD * 2);
    const int rowB = (lane & 7) + ((g >> 1) ? 8 : 0);
    const uint32_t offB0 = rowB * (APAD * 2) + (g & 1) * 16;
    const uint32_t offB1 = offB0 + 16 * (APAD * 2);

    float acc[2][4][4];
    #pragma unroll
    for (int ti = 0; ti < 2; ti++)
        #pragma unroll
        for (int j = 0; j < 4; j++)
            #pragma unroll
            for (int i = 0; i < 4; i++) acc[ti][j][i] = 0.f;

    float4 aR[16];
    uint4  bhR[2], blR[2];

    auto fetch = [&](int c) {
        const float* ap = Ap + c * 64;
        #pragma unroll
        for (int i = 0; i < 16; i++) aR[i] = *(const float4*)(ap + aoff[i]);
        #pragma unroll
        for (int i = 0; i < 2; i++) {
            bhR[i] = *(const uint4*)(Bgh + boffB[i] + c * 64);
            blR[i] = *(const uint4*)(Bgl + boffB[i] + c * 64);
        }
    };
    auto stage = [&]() {
        #pragma unroll
        for (int i = 0; i < 16; i++) {
            float4 f = aR[i];
            uint32_t h01 = cvt_bf16x2(f.y, f.x);
            uint32_t h23 = cvt_bf16x2(f.w, f.z);
            float g0 = __uint_as_float(h01 << 16);
            float g1 = __uint_as_float(h01 & 0xFFFF0000u);
            float g2 = __uint_as_float(h23 << 16);
            float g3 = __uint_as_float(h23 & 0xFFFF0000u);
            uint32_t l01 = cvt_bf16x2(f.y - g1, f.x - g0);
            uint32_t l23 = cvt_bf16x2(f.w - g3, f.z - g2);
            *(uint2*)(smem + SM_AH + smA[i]) = make_uint2(h01, h23);
            *(uint2*)(smem + SM_AL + smA[i]) = make_uint2(l01, l23);
        }
        #pragma unroll
        for (int i = 0; i < 2; i++) {
            *(uint4*)(smem + SM_BH + smB[i]) = bhR[i];
            *(uint4*)(smem + SM_BL + smB[i]) = blR[i];
        }
    };

    fetch(0);
    stage();
    __syncthreads();

    for (int c = 0; c < NC; c++) {
        if (c + 1 < NC) fetch(c + 1);

        #pragma unroll
        for (int ks = 0; ks < 4; ks++) {
            uint32_t ah0[4], al0[4], ah1[4], al1[4], bh[8], bl[8];
            ldsm4(ah0, sb + SM_AH + offA0 + ks * 32);
            ldsm4(ah1, sb + SM_AH + offA1 + ks * 32);
            ldsm4(al0, sb + SM_AL + offA0 + ks * 32);
            ldsm4(al1, sb + SM_AL + offA1 + ks * 32);
            ldsm4(bh,     sb + SM_BH + offB0 + ks * 32);
            ldsm4(bh + 4, sb + SM_BH + offB1 + ks * 32);
            ldsm4(bl,     sb + SM_BL + offB0 + ks * 32);
            ldsm4(bl + 4, sb + SM_BL + offB1 + ks * 32);
            #pragma unroll
            for (int j = 0; j < 4; j++) {
                mma16816(acc[0][j], ah0, bh[2 * j], bh[2 * j + 1]);
                mma16816(acc[0][j], ah0, bl[2 * j], bl[2 * j + 1]);
                mma16816(acc[0][j], al0, bh[2 * j], bh[2 * j + 1]);
                mma16816(acc[1][j], ah1, bh[2 * j], bh[2 * j + 1]);
                mma16816(acc[1][j], ah1, bl[2 * j], bl[2 * j + 1]);
                mma16816(acc[1][j], al1, bh[2 * j], bh[2 * j + 1]);
            }
        }
        __syncthreads();
        if (c + 1 < NC) {
            stage();
            __syncthreads();
        }
    }

    // Epilogue: transpose through smem, split bf16 hi/lo, store [t][n][m]
    const int cg = lane >> 2;
    const int tc = (lane & 3) * 2;
    float* S = (float*)smem;     // [32][132] fp32 (smem reused)
    #pragma unroll
    for (int ti = 0; ti < 2; ti++) {
        int m = wid * 32 + ti * 16 + cg;
        #pragma unroll
        for (int j = 0; j < 4; j++) {
            int n = j * 8 + tc;
            S[n * 132 + m]           = acc[ti][j][0];
            S[(n + 1) * 132 + m]     = acc[ti][j][1];
            S[n * 132 + m + 8]       = acc[ti][j][2];
            S[(n + 1) * 132 + m + 8] = acc[ti][j][3];
        }
    }
    __syncthreads();
    const int n  = tid >> 2;
    const int ms = (tid & 3) * 32;
    float v[32];
    #pragma unroll
    for (int i = 0; i < 8; i++)
        *(float4*)&v[i * 4] = *(const float4*)&S[n * 132 + ms + i * 4];
    uint32_t hp[16], lp[16];
    #pragma unroll
    for (int i = 0; i < 16; i++) {
        hp[i] = cvt_bf16x2(v[2 * i + 1], v[2 * i]);
        float g0 = __uint_as_float(hp[i] << 16);
        float g1 = __uint_as_float(hp[i] & 0xFFFF0000u);
        lp[i] = cvt_bf16x2(v[2 * i + 1] - g1, v[2 * i] - g0);
    }
    long ooff = ((long)t * CDIM + n) * NNODES + mb * 128 + ms;  // ushort units
    #pragma unroll
    for (int i = 0; i < 4; i++) {
        *(uint4*)(OTh + ooff + i * 8) =
            make_uint4(hp[4 * i], hp[4 * i + 1], hp[4 * i + 2], hp[4 * i + 3]);
        *(uint4*)(OTl + ooff + i * 8) =
            make_uint4(lp[4 * i], lp[4 * i + 1], lp[4 * i + 2], lp[4 * i + 3]);
    }
}

// ---------------------------------------------------------------------------
// AY: out_t = relu(A_t @ Y_t) — cp.async CH=64 2-stage, 256 threads
// (measured 208us in R13; unchanged).
// ---------------------------------------------------------------------------
#define AFP 72                              // fp32 pitch for A smem
#define BPD 72                              // bf16 pitch for B smem
#define ASTG (128 * AFP * 4)                // 36864 B per A stage
#define BSTG (32 * BPD * 2)                 // 4608 B per B stage
#define OFF_A(s)  ((s) * ASTG)
#define OFF_BH(s) (2 * ASTG + (s) * BSTG)
#define OFF_BL(s) (2 * ASTG + 2 * BSTG + (s) * BSTG)
#define SMEM_BYTES (2 * ASTG + 4 * BSTG)    // 92160 B

__global__ void __launch_bounds__(256, 2) ay_mma(
    const float* __restrict__ Abase,
    const unsigned short* __restrict__ Bhb,
    const unsigned short* __restrict__ Blb,
    float* __restrict__ Out) {

    constexpr int NC = 64;
    constexpr int K  = NC * 64;   // 4096
    extern __shared__ __align__(16) unsigned char smem[];
    const uint32_t sb = smem_u32(smem);

    const int tid  = threadIdx.x;
    const int wid  = tid >> 5;         // 0..7, warp owns rows wid*16..+15
    const int lane = tid & 31;
    const int t    = blockIdx.y;
    const int mb   = blockIdx.x;

    const float* Ap = Abase + ((long)t * NNODES + (long)mb * 128) * K;
    const unsigned short* Bgh = Bhb + (long)t * CDIM * K;
    const unsigned short* Bgl = Blb + (long)t * CDIM * K;

    // ldmatrix B lane offsets (byte)
    const int g = lane >> 3;
    const int rowB = (lane & 7) + ((g >> 1) ? 8 : 0);
    const uint32_t offB0 = rowB * (BPD * 2) + (g & 1) * 16;
    const uint32_t offB1 = offB0 + 16 * (BPD * 2);

    // A fragment lane offsets (fp32 smem)
    const int g4 = lane >> 2;
    const int t2 = (lane & 3) * 2;

    float acc[4][4];
    #pragma unroll
    for (int j = 0; j < 4; j++)
        #pragma unroll
        for (int i = 0; i < 4; i++) acc[j][i] = 0.f;

    auto load_async = [&](int c, int s) {
        const float* ap = Ap + c * 64;
        #pragma unroll
        for (int i = 0; i < 8; i++) {
            int idx = tid + i * 256;
            int m = idx >> 4, j = idx & 15;
            cpasync16(sb + OFF_A(s) + (m * AFP + j * 4) * 4,
                      ap + (long)m * K + j * 4);
        }
        {
            int n = tid >> 3, jj = tid & 7;
            long go = (long)n * K + c * 64 + jj * 8;
            uint32_t so = (n * BPD + jj * 8) * 2;
            cpasync16(sb + OFF_BH(s) + so, Bgh + go);
            cpasync16(sb + OFF_BL(s) + so, Bgl + go);
        }
        cp_commit();
    };

    auto compute = [&](int s) {
        const uint32_t aBase = sb + OFF_A(s);
        const uint32_t bhB   = sb + OFF_BH(s);
        const uint32_t blB   = sb + OFF_BL(s);
        #pragma unroll
        for (int ks = 0; ks < 4; ks++) {
            uint32_t bh[8], bl[8];
            ldsm4(bh,     bhB + offB0 + ks * 32);
            ldsm4(bh + 4, bhB + offB1 + ks * 32);
            ldsm4(bl,     blB + offB0 + ks * 32);
            ldsm4(bl + 4, blB + offB1 + ks * 32);
            uint32_t pa = aBase + (((wid * 16 + g4) * AFP) + ks * 16 + t2) * 4;
            float2 x0 = ldsf2(pa);
            float2 x1 = ldsf2(pa + 8 * AFP * 4);
            float2 x2 = ldsf2(pa + 32);
            float2 x3 = ldsf2(pa + 8 * AFP * 4 + 32);
            uint32_t ah[4], al[4];
            split2(x0, ah[0], al[0]);
            split2(x1, ah[1], al[1]);
            split2(x2, ah[2], al[2]);
            split2(x3, ah[3], al[3]);
            #pragma unroll
            for (int j = 0; j < 4; j++) {
                mma16816(acc[j], ah, bh[2 * j], bh[2 * j + 1]);
                mma16816(acc[j], ah, bl[2 * j], bl[2 * j + 1]);
                mma16816(acc[j], al, bh[2 * j], bh[2 * j + 1]);
            }
        }
    };

    load_async(0, 0);
    for (int c = 0; c < NC; c++) {
        int buf = c & 1;
        if (c + 1 < NC) {
            load_async(c + 1, buf ^ 1);
            asm volatile("cp.async.wait_group 1;" ::: "memory");
        } else {
            asm volatile("cp.async.wait_group 0;" ::: "memory");
        }
        __syncthreads();
        compute(buf);
        __syncthreads();
    }

    // Epilogue: relu + direct store [t][m][n]
    const int cg = lane >> 2;
    const int tc = (lane & 3) * 2;
    const long row0 = (long)t * NNODES + mb * 128 + wid * 16 + cg;
    #pragma unroll
    for (int j = 0; j < 4; j++) {
        float2 v0, v1;
        v0.x = fmaxf(acc[j][0], 0.f);
        v0.y = fmaxf(acc[j][1], 0.f);
        v1.x = fmaxf(acc[j][2], 0.f);
        v1.y = fmaxf(acc[j][3], 0.f);
        *(float2*)(Out + row0 * CDIM + j * 8 + tc)       = v0;
        *(float2*)(Out + (row0 + 8) * CDIM + j * 8 + tc) = v1;
    }
}

// ---------------------------------------------------------------------------
// Launch: GRU (persistent, fold inline) -> XQ (static) -> AY (256-thread)
// ---------------------------------------------------------------------------
extern "C" void kernel_launch(void* const* d_in, const int* in_sizes, int n_in,
                              void* d_out, int out_size) {
    const float* A  = (const float*)d_in[0];   // [1,16,4096,4096]
    const float* X  = (const float*)d_in[1];   // [16,4096,256]
    const float* Q0 = (const float*)d_in[2];   // [256,32]
    const float* Wz = (const float*)d_in[3];
    const float* Uz = (const float*)d_in[4];
    const float* Wr = (const float*)d_in[5];
    const float* Ur = (const float*)d_in[6];
    const float* Wh = (const float*)d_in[7];
    const float* Uh = (const float*)d_in[8];
    float* out = (float*)d_out;                // [16,4096,32]

    void *pQh = nullptr, *pQl = nullptr, *pYh = nullptr, *pYl = nullptr;
    cudaGetSymbolAddress(&pQh, g_Qth);
    cudaGetSymbolAddress(&pQl, g_Qtl);
    cudaGetSymbolAddress(&pYh, g_Yth);
    cudaGetSymbolAddress(&pYl, g_Ytl);

    cudaFuncSetAttribute(gru_persist,
                         cudaFuncAttributeMaxDynamicSharedMemorySize, GRU_SMEM);
    cudaFuncSetAttribute(ay_mma,
                         cudaFuncAttributeMaxDynamicSharedMemorySize, SMEM_BYTES);

    // 1. Evolve Q over 16 steps (32 persistent blocks; gate-fold inline)
    gru_persist<<<GRU_NB, 256, GRU_SMEM>>>(Q0, Wz, Uz, Wr, Ur, Wh, Uh);

    // 2. Y_t = X_t @ Q_t (static-smem tensor kernel) -> Y^T bf16 hi/lo
    xq_mma<<<dim3(NNODES / 128, TSTEPS), 128>>>(
        X, (const unsigned short*)pQh, (const unsigned short*)pQl,
        (unsigned short*)pYh, (unsigned short*)pYl);

    // 3. out_t = relu(A_t @ Y_t) (cp.async, 8 warps)
    ay_mma<<<dim3(NNODES / 128, TSTEPS), 256, SMEM_BYTES>>>(
        A, (const unsigned short*)pYh, (const unsigned short*)pYl, out);
}

// round 17
// speedup vs baseline: 1.6554x; 1.0291x over previous
#include <cuda_runtime.h>
#include <cuda_bf16.h>
#include <cstdint>
#include <math.h>

// Problem dims (fixed by dataset)
#define TSTEPS 16
#define NNODES 4096
#define RDIM   256
#define CDIM   32

// Scratch (static device globals — no allocation)
// q / rq live in the interleaved layout: flat[((r>>2)*32 + c)*4 + (r&3)]
// i.e. [k4][c] float4 groups — conflict-free lane-major smem reads.
__device__ float g_q [CDIM * RDIM];
__device__ float g_rq[CDIM * RDIM];
// Barrier state: each on its OWN 128B L2 line (no false sharing between the
// arrival-atomic line and the line 31 blocks spin-poll).
__device__ __align__(128) unsigned g_bar_cnt;             // arrivals (0 at rest)
__device__ __align__(128) unsigned g_bar_gen;             // generation
__device__ unsigned short g_Qth[TSTEPS * CDIM * RDIM];    // Q^T hi bf16 [t][n][k]
__device__ unsigned short g_Qtl[TSTEPS * CDIM * RDIM];    // Q^T lo bf16
__device__ unsigned short g_Yth[TSTEPS * CDIM * NNODES];  // Y^T hi bf16 [t][n][k]
__device__ unsigned short g_Ytl[TSTEPS * CDIM * NNODES];  // Y^T lo bf16

// ---------------------------------------------------------------------------
// Small PTX helpers
// ---------------------------------------------------------------------------
__device__ __forceinline__ uint32_t smem_u32(const void* p) {
    uint32_t a;
    asm("{ .reg .u64 t; cvta.to.shared.u64 t, %1; cvt.u32.u64 %0, t; }"
        : "=r"(a) : "l"(p));
    return a;
}
__device__ __forceinline__ uint32_t cvt_bf16x2(float hi, float lo) {
    uint32_t r;
    asm("cvt.rn.bf16x2.f32 %0, %1, %2;" : "=r"(r) : "f"(hi), "f"(lo));
    return r;
}
__device__ __forceinline__ void ldsm4(uint32_t* r, uint32_t a) {
    asm volatile("ldmatrix.sync.aligned.m8n8.x4.shared.b16 {%0,%1,%2,%3}, [%4];"
                 : "=r"(r[0]), "=r"(r[1]), "=r"(r[2]), "=r"(r[3]) : "r"(a));
}
__device__ __forceinline__ void mma16816(float* c, const uint32_t* a,
                                         uint32_t b0, uint32_t b1) {
    asm volatile(
        "mma.sync.aligned.m16n8k16.row.col.f32.bf16.bf16.f32 "
        "{%0,%1,%2,%3}, {%4,%5,%6,%7}, {%8,%9}, {%0,%1,%2,%3};"
        : "+f"(c[0]), "+f"(c[1]), "+f"(c[2]), "+f"(c[3])
        : "r"(a[0]), "r"(a[1]), "r"(a[2]), "r"(a[3]), "r"(b0), "r"(b1));
}
__device__ __forceinline__ float2 ldsf2(uint32_t a) {
    float2 v;
    asm volatile("ld.shared.v2.f32 {%0,%1}, [%2];" : "=f"(v.x), "=f"(v.y) : "r"(a));
    return v;
}
__device__ __forceinline__ void cpasync16(uint32_t s, const void* g) {
    asm volatile("cp.async.cg.shared.global [%0], [%1], 16;" :: "r"(s), "l"(g));
}
__device__ __forceinline__ void cp_commit() {
    asm volatile("cp.async.commit_group;" ::: "memory");
}
// Split fp32 pair -> bf16x2 hi (lower=f.x) + bf16x2 residual lo
__device__ __forceinline__ void split2(float2 f, uint32_t& h, uint32_t& l) {
    h = cvt_bf16x2(f.y, f.x);
    float gx = __uint_as_float(h << 16);
    float gy = __uint_as_float(h & 0xFFFF0000u);
    l = cvt_bf16x2(f.y - gy, f.x - gx);
}
// Packed fp32x2 FMA (Blackwell f32x2 pipe — 2 FMAs per issue)
__device__ __forceinline__ void ffma2(unsigned long long& d, unsigned long long a,
                                      unsigned long long b) {
    asm("fma.rn.f32x2 %0, %1, %2, %0;" : "+l"(d) : "l"(a), "l"(b));
}

// ---------------------------------------------------------------------------
// Software grid barrier: 32 blocks, all guaranteed resident.
// Cumulative-fence pattern (standard cooperative-groups grid sync): all
// threads __syncthreads, thread 0 fences + arrives; PTX fence cumulativity
// makes every thread's prior stores visible to post-barrier observers.
// NO per-thread __threadfence anywhere else.
// ---------------------------------------------------------------------------
#define GRU_NB 32
__device__ __forceinline__ void gsync() {
    __syncthreads();
    if (threadIdx.x == 0) {
        __threadfence();
        unsigned gen = *(volatile unsigned*)&g_bar_gen;
        if (atomicAdd(&g_bar_cnt, 1u) == GRU_NB - 1) {
            g_bar_cnt = 0;
            __threadfence();
            atomicAdd(&g_bar_gen, 1u);
        } else {
            while (*(volatile unsigned*)&g_bar_gen == gen) { }
        }
        __threadfence();
    }
    __syncthreads();
}

// ---------------------------------------------------------------------------
// GRU evolution of Q [256,32] over 16 steps — persistent weights-in-smem.
// Interleaved [k4][c] float4 q/rq layout (conflict-free lane reads), packed
// f32x2 FMA accumulation, gate-fold inline during the one-time weight load.
// 32 blocks x 256 threads; block owns 8 rows; thread (w=row-local, c=column).
// ---------------------------------------------------------------------------
#define GRU_SMEM (24576 * 4)   // 96 KB: 4 x 8x256 weights + 2 x 8K q/rq

__global__ void __launch_bounds__(256, 1) gru_persist(
    const float* __restrict__ Q0,
    const float* __restrict__ Wzg, const float* __restrict__ Uzg,
    const float* __restrict__ Wrg, const float* __restrict__ Urg,
    const float* __restrict__ Whg, const float* __restrict__ Uhg) {
    extern __shared__ float sm[];
    float* wz = sm;            // [8][256]  (Wz+Uz folded)
    float* wr = sm + 2048;     // [8][256]  (Wr+Ur folded)
    float* wh = sm + 4096;
    float* uh = sm + 6144;
    float* qs = sm + 8192;     // interleaved [k4][c] float4 = 8192 floats
    float* rs = sm + 16384;

    const int tid = threadIdx.x;
    const int w = tid >> 5, c = tid & 31;
    const int r0 = blockIdx.x * 8;
    const int r  = r0 + w;                 // this thread's output row
    const int own = ((r >> 2) * 32 + c) * 4 + (r & 3);   // interleaved index

    // One-time: load this block's 8 rows of all matrices, folding gates.
    #pragma unroll
    for (int i = 0; i < 2; i++) {
        int idx = tid + i * 256;          // 512 float4 per matrix
        int row = idx >> 6, j = (idx & 63) * 4;
        long src = (long)(r0 + row) * RDIM + j;
        float4 a1 = *(const float4*)&Wzg[src];
        float4 a2 = *(const float4*)&Uzg[src];
        *(float4*)&wz[row * 256 + j] =
            make_float4(a1.x + a2.x, a1.y + a2.y, a1.z + a2.z, a1.w + a2.w);
        float4 b1 = *(const float4*)&Wrg[src];
        float4 b2 = *(const float4*)&Urg[src];
        *(float4*)&wr[row * 256 + j] =
            make_float4(b1.x + b2.x, b1.y + b2.y, b1.z + b2.z, b1.w + b2.w);
        *(float4*)&wh[row * 256 + j] = *(const float4*)&Whg[src];
        *(float4*)&uh[row * 256 + j] = *(const float4*)&Uhg[src];
    }
    // Init q (interleaved layout).
    g_q[own] = Q0[r * CDIM + c];
    gsync();

    for (int t = 0; t < TSTEPS; t++) {
        // Stage q (straight copy — same layout both sides)
        #pragma unroll
        for (int i = 0; i < 8; i++) {
            int idx = (tid + i * 256) * 4;
            *(float4*)&qs[idx] = *(const float4*)&g_q[idx];
        }
        __syncthreads();

        // Phase 1: gates via packed f32x2 dot products.
        unsigned long long sz2 = 0ull, sr2 = 0ull;
        #pragma unroll 8
        for (int k4 = 0; k4 < 64; k4++) {
            ulonglong2 wzv = *(const ulonglong2*)&wz[w * 256 + k4 * 4];
            ulonglong2 wrv = *(const ulonglong2*)&wr[w * 256 + k4 * 4];
            ulonglong2 qv  = *(const ulonglong2*)&qs[(k4 * 32 + c) * 4];
            ffma2(sz2, wzv.x, qv.x); ffma2(sz2, wzv.y, qv.y);
            ffma2(sr2, wrv.x, qv.x); ffma2(sr2, wrv.y, qv.y);
        }
        float2 szp = *(float2*)&sz2;
        float2 srp = *(float2*)&sr2;
        float sz = szp.x + szp.y;
        float sr = srp.x + srp.y;
        float z    = 1.f / (1.f + expf(-sz));
        float rg   = 1.f / (1.f + expf(-sr));
        float qown = qs[own];
        g_rq[own] = rg * qown;
        gsync();

        // Stage rq
        #pragma unroll
        for (int i = 0; i < 8; i++) {
            int idx = (tid + i * 256) * 4;
            *(float4*)&rs[idx] = *(const float4*)&g_rq[idx];
        }
        __syncthreads();

        // Phase 2: candidate.
        unsigned long long sh2 = 0ull;
        #pragma unroll 8
        for (int k4 = 0; k4 < 64; k4++) {
            ulonglong2 whv = *(const ulonglong2*)&wh[w * 256 + k4 * 4];
            ulonglong2 uhv = *(const ulonglong2*)&uh[w * 256 + k4 * 4];
            ulonglong2 qv  = *(const ulonglong2*)&qs[(k4 * 32 + c) * 4];
            ulonglong2 rv  = *(const ulonglong2*)&rs[(k4 * 32 + c) * 4];
            ffma2(sh2, whv.x, qv.x); ffma2(sh2, whv.y, qv.y);
            ffma2(sh2, uhv.x, rv.x); ffma2(sh2, uhv.y, rv.y);
        }
        float2 shp = *(float2*)&sh2;
        float sh = shp.x + shp.y;
        float h  = tanhf(sh);
        float qn = (1.f - z) * qown + z * h;
        g_q[own] = qn;

        // Emit Q^T bf16 hi/lo at [t][c][r]
        uint32_t ph = cvt_bf16x2(0.f, qn);
        float    hf = __uint_as_float(ph << 16);
        uint32_t pl = cvt_bf16x2(0.f, qn - hf);
        long qoff = ((long)t * CDIM + c) * RDIM + r;
        g_Qth[qoff] = (unsigned short)(ph & 0xFFFFu);
        g_Qtl[qoff] = (unsigned short)(pl & 0xFFFFu);
        gsync();
    }
}

// ---------------------------------------------------------------------------
// XQ: Y_t = X_t @ Q_t (static-smem register-staged kernel; measured-good,
// unchanged).
// ---------------------------------------------------------------------------
#define APAD 72
#define SM_AH 0
#define SM_AL (128 * APAD * 2)
#define SM_BH (2 * 128 * APAD * 2)
#define SM_BL (2 * 128 * APAD * 2 + 32 * APAD * 2)
#define SM_TOT (2 * 128 * APAD * 2 + 2 * 32 * APAD * 2)

__global__ void __launch_bounds__(128, 3) xq_mma(
    const float* __restrict__ Abase,
    const unsigned short* __restrict__ Bhb,
    const unsigned short* __restrict__ Blb,
    unsigned short* __restrict__ OTh,
    unsigned short* __restrict__ OTl) {

    constexpr int NC = 4;
    constexpr int K  = NC * 64;   // 256
    __shared__ __align__(16) unsigned char smem[SM_TOT];

    const int tid  = threadIdx.x;
    const int wid  = tid >> 5;
    const int lane = tid & 31;
    const int t    = blockIdx.y;
    const int mb   = blockIdx.x;

    const float* Ap = Abase + ((long)t * NNODES + (long)mb * 128) * K;
    const unsigned short* Bgh = Bhb + (long)t * CDIM * K;
    const unsigned short* Bgl = Blb + (long)t * CDIM * K;

    int aoff[16];
    int smA[16];   // byte offsets
    #pragma unroll
    for (int i = 0; i < 16; i++) {
        int idx = tid + i * 128;
        int m = idx >> 4, qd = idx & 15;
        aoff[i] = m * K + qd * 4;
        smA[i]  = (m * APAD + qd * 4) * 2;
    }
    int boffB[2], smB[2];
    #pragma unroll
    for (int i = 0; i < 2; i++) {
        int idx = tid + i * 128;
        int bn = idx >> 3, bq = idx & 7;
        boffB[i] = bn * K + bq * 8;     // ushort units
        smB[i]   = (bn * APAD + bq * 8) * 2;
    }

    const uint32_t sb = smem_u32(smem);
    const int g = lane >> 3;
    const int rowA = wid * 32 + (lane & 7) + ((g & 1) ? 8 : 0);
    const uint32_t offA0 = rowA * (APAD * 2) + (g >> 1) * 16;
    const uint32_t offA1 = offA0 + 16 * (APAD * 2);
    const int rowB = (lane & 7) + ((g >> 1) ? 8 : 0);
    const uint32_t offB0 = rowB * (APAD * 2) + (g & 1) * 16;
    const uint32_t offB1 = offB0 + 16 * (APAD * 2);

    float acc[2][4][4];
    #pragma unroll
    for (int ti = 0; ti < 2; ti++)
        #pragma unroll
        for (int j = 0; j < 4; j++)
            #pragma unroll
            for (int i = 0; i < 4; i++) acc[ti][j][i] = 0.f;

    float4 aR[16];
    uint4  bhR[2], blR[2];

    auto fetch = [&](int c) {
        const float* ap = Ap + c * 64;
        #pragma unroll
        for (int i = 0; i < 16; i++) aR[i] = *(const float4*)(ap + aoff[i]);
        #pragma unroll
        for (int i = 0; i < 2; i++) {
            bhR[i] = *(const uint4*)(Bgh + boffB[i] + c * 64);
            blR[i] = *(const uint4*)(Bgl + boffB[i] + c * 64);
        }
    };
    auto stage = [&]() {
        #pragma unroll
        for (int i = 0; i < 16; i++) {
            float4 f = aR[i];
            uint32_t h01 = cvt_bf16x2(f.y, f.x);
            uint32_t h23 = cvt_bf16x2(f.w, f.z);
            float g0 = __uint_as_float(h01 << 16);
            float g1 = __uint_as_float(h01 & 0xFFFF0000u);
            float g2 = __uint_as_float(h23 << 16);
            float g3 = __uint_as_float(h23 & 0xFFFF0000u);
            uint32_t l01 = cvt_bf16x2(f.y - g1, f.x - g0);
            uint32_t l23 = cvt_bf16x2(f.w - g3, f.z - g2);
            *(uint2*)(smem + SM_AH + smA[i]) = make_uint2(h01, h23);
            *(uint2*)(smem + SM_AL + smA[i]) = make_uint2(l01, l23);
        }
        #pragma unroll
        for (int i = 0; i < 2; i++) {
            *(uint4*)(smem + SM_BH + smB[i]) = bhR[i];
            *(uint4*)(smem + SM_BL + smB[i]) = blR[i];
        }
    };

    fetch(0);
    stage();
    __syncthreads();

    for (int c = 0; c < NC; c++) {
        if (c + 1 < NC) fetch(c + 1);

        #pragma unroll
        for (int ks = 0; ks < 4; ks++) {
            uint32_t ah0[4], al0[4], ah1[4], al1[4], bh[8], bl[8];
            ldsm4(ah0, sb + SM_AH + offA0 + ks * 32);
            ldsm4(ah1, sb + SM_AH + offA1 + ks * 32);
            ldsm4(al0, sb + SM_AL + offA0 + ks * 32);
            ldsm4(al1, sb + SM_AL + offA1 + ks * 32);
            ldsm4(bh,     sb + SM_BH + offB0 + ks * 32);
            ldsm4(bh + 4, sb + SM_BH + offB1 + ks * 32);
            ldsm4(bl,     sb + SM_BL + offB0 + ks * 32);
            ldsm4(bl + 4, sb + SM_BL + offB1 + ks * 32);
            #pragma unroll
            for (int j = 0; j < 4; j++) {
                mma16816(acc[0][j], ah0, bh[2 * j], bh[2 * j + 1]);
                mma16816(acc[0][j], ah0, bl[2 * j], bl[2 * j + 1]);
                mma16816(acc[0][j], al0, bh[2 * j], bh[2 * j + 1]);
                mma16816(acc[1][j], ah1, bh[2 * j], bh[2 * j + 1]);
                mma16816(acc[1][j], ah1, bl[2 * j], bl[2 * j + 1]);
                mma16816(acc[1][j], al1, bh[2 * j], bh[2 * j + 1]);
            }
        }
        __syncthreads();
        if (c + 1 < NC) {
            stage();
            __syncthreads();
        }
    }

    // Epilogue: transpose through smem, split bf16 hi/lo, store [t][n][m]
    const int cg = lane >> 2;
    const int tc = (lane & 3) * 2;
    float* S = (float*)smem;     // [32][132] fp32 (smem reused)
    #pragma unroll
    for (int ti = 0; ti < 2; ti++) {
        int m = wid * 32 + ti * 16 + cg;
        #pragma unroll
        for (int j = 0; j < 4; j++) {
            int n = j * 8 + tc;
            S[n * 132 + m]           = acc[ti][j][0];
            S[(n + 1) * 132 + m]     = acc[ti][j][1];
            S[n * 132 + m + 8]       = acc[ti][j][2];
            S[(n + 1) * 132 + m + 8] = acc[ti][j][3];
        }
    }
    __syncthreads();
    const int n  = tid >> 2;
    const int ms = (tid & 3) * 32;
    float v[32];
    #pragma unroll
    for (int i = 0; i < 8; i++)
        *(float4*)&v[i * 4] = *(const float4*)&S[n * 132 + ms + i * 4];
    uint32_t hp[16], lp[16];
    #pragma unroll
    for (int i = 0; i < 16; i++) {
        hp[i] = cvt_bf16x2(v[2 * i + 1], v[2 * i]);
        float g0 = __uint_as_float(hp[i] << 16);
        float g1 = __uint_as_float(hp[i] & 0xFFFF0000u);
        lp[i] = cvt_bf16x2(v[2 * i + 1] - g1, v[2 * i] - g0);
    }
    long ooff = ((long)t * CDIM + n) * NNODES + mb * 128 + ms;  // ushort units
    #pragma unroll
    for (int i = 0; i < 4; i++) {
        *(uint4*)(OTh + ooff + i * 8) =
            make_uint4(hp[4 * i], hp[4 * i + 1], hp[4 * i + 2], hp[4 * i + 3]);
        *(uint4*)(OTl + ooff + i * 8) =
            make_uint4(lp[4 * i], lp[4 * i + 1], lp[4 * i + 2], lp[4 * i + 3]);
    }
}

// ---------------------------------------------------------------------------
// AY: out_t = relu(A_t @ Y_t) — cp.async CH=64 2-stage, 256 threads
// (measured 208us; unchanged).
// ---------------------------------------------------------------------------
#define AFP 72                              // fp32 pitch for A smem
#define BPD 72                              // bf16 pitch for B smem
#define ASTG (128 * AFP * 4)                // 36864 B per A stage
#define BSTG (32 * BPD * 2)                 // 4608 B per B stage
#define OFF_A(s)  ((s) * ASTG)
#define OFF_BH(s) (2 * ASTG + (s) * BSTG)
#define OFF_BL(s) (2 * ASTG + 2 * BSTG + (s) * BSTG)
#define SMEM_BYTES (2 * ASTG + 4 * BSTG)    // 92160 B

__global__ void __launch_bounds__(256, 2) ay_mma(
    const float* __restrict__ Abase,
    const unsigned short* __restrict__ Bhb,
    const unsigned short* __restrict__ Blb,
    float* __restrict__ Out) {

    constexpr int NC = 64;
    constexpr int K  = NC * 64;   // 4096
    extern __shared__ __align__(16) unsigned char smem[];
    const uint32_t sb = smem_u32(smem);

    const int tid  = threadIdx.x;
    const int wid  = tid >> 5;         // 0..7, warp owns rows wid*16..+15
    const int lane = tid & 31;
    const int t    = blockIdx.y;
    const int mb   = blockIdx.x;

    const float* Ap = Abase + ((long)t * NNODES + (long)mb * 128) * K;
    const unsigned short* Bgh = Bhb + (long)t * CDIM * K;
    const unsigned short* Bgl = Blb + (long)t * CDIM * K;

    // ldmatrix B lane offsets (byte)
    const int g = lane >> 3;
    const int rowB = (lane & 7) + ((g >> 1) ? 8 : 0);
    const uint32_t offB0 = rowB * (BPD * 2) + (g & 1) * 16;
    const uint32_t offB1 = offB0 + 16 * (BPD * 2);

    // A fragment lane offsets (fp32 smem)
    const int g4 = lane >> 2;
    const int t2 = (lane & 3) * 2;

    float acc[4][4];
    #pragma unroll
    for (int j = 0; j < 4; j++)
        #pragma unroll
        for (int i = 0; i < 4; i++) acc[j][i] = 0.f;

    auto load_async = [&](int c, int s) {
        const float* ap = Ap + c * 64;
        #pragma unroll
        for (int i = 0; i < 8; i++) {
            int idx = tid + i * 256;
            int m = idx >> 4, j = idx & 15;
            cpasync16(sb + OFF_A(s) + (m * AFP + j * 4) * 4,
                      ap + (long)m * K + j * 4);
        }
        {
            int n = tid >> 3, jj = tid & 7;
            long go = (long)n * K + c * 64 + jj * 8;
            uint32_t so = (n * BPD + jj * 8) * 2;
            cpasync16(sb + OFF_BH(s) + so, Bgh + go);
            cpasync16(sb + OFF_BL(s) + so, Bgl + go);
        }
        cp_commit();
    };

    auto compute = [&](int s) {
        const uint32_t aBase = sb + OFF_A(s);
        const uint32_t bhB   = sb + OFF_BH(s);
        const uint32_t blB   = sb + OFF_BL(s);
        #pragma unroll
        for (int ks = 0; ks < 4; ks++) {
            uint32_t bh[8], bl[8];
            ldsm4(bh,     bhB + offB0 + ks * 32);
            ldsm4(bh + 4, bhB + offB1 + ks * 32);
            ldsm4(bl,     blB + offB0 + ks * 32);
            ldsm4(bl + 4, blB + offB1 + ks * 32);
            uint32_t pa = aBase + (((wid * 16 + g4) * AFP) + ks * 16 + t2) * 4;
            float2 x0 = ldsf2(pa);
            float2 x1 = ldsf2(pa + 8 * AFP * 4);
            float2 x2 = ldsf2(pa + 32);
            float2 x3 = ldsf2(pa + 8 * AFP * 4 + 32);
            uint32_t ah[4], al[4];
            split2(x0, ah[0], al[0]);
            split2(x1, ah[1], al[1]);
            split2(x2, ah[2], al[2]);
            split2(x3, ah[3], al[3]);
            #pragma unroll
            for (int j = 0; j < 4; j++) {
                mma16816(acc[j], ah, bh[2 * j], bh[2 * j + 1]);
                mma16816(acc[j], ah, bl[2 * j], bl[2 * j + 1]);
                mma16816(acc[j], al, bh[2 * j], bh[2 * j + 1]);
            }
        }
    };

    load_async(0, 0);
    for (int c = 0; c < NC; c++) {
        int buf = c & 1;
        if (c + 1 < NC) {
            load_async(c + 1, buf ^ 1);
            asm volatile("cp.async.wait_group 1;" ::: "memory");
        } else {
            asm volatile("cp.async.wait_group 0;" ::: "memory");
        }
        __syncthreads();
        compute(buf);
        __syncthreads();
    }

    // Epilogue: relu + direct store [t][m][n]
    const int cg = lane >> 2;
    const int tc = (lane & 3) * 2;
    const long row0 = (long)t * NNODES + mb * 128 + wid * 16 + cg;
    #pragma unroll
    for (int j = 0; j < 4; j++) {
        float2 v0, v1;
        v0.x = fmaxf(acc[j][0], 0.f);
        v0.y = fmaxf(acc[j][1], 0.f);
        v1.x = fmaxf(acc[j][2], 0.f);
        v1.y = fmaxf(acc[j][3], 0.f);
        *(float2*)(Out + row0 * CDIM + j * 8 + tc)       = v0;
        *(float2*)(Out + (row0 + 8) * CDIM + j * 8 + tc) = v1;
    }
}

// ---------------------------------------------------------------------------
// Launch: GRU (persistent, cheap barriers) -> XQ (static) -> AY (256-thread)
// ---------------------------------------------------------------------------
extern "C" void kernel_launch(void* const* d_in, const int* in_sizes, int n_in,
                              void* d_out, int out_size) {
    const float* A  = (const float*)d_in[0];   // [1,16,4096,4096]
    const float* X  = (const float*)d_in[1];   // [16,4096,256]
    const float* Q0 = (const float*)d_in[2];   // [256,32]
    const float* Wz = (const float*)d_in[3];
    const float* Uz = (const float*)d_in[4];
    const float* Wr = (const float*)d_in[5];
    const float* Ur = (const float*)d_in[6];
    const float* Wh = (const float*)d_in[7];
    const float* Uh = (const float*)d_in[8];
    float* out = (float*)d_out;                // [16,4096,32]

    void *pQh = nullptr, *pQl = nullptr, *pYh = nullptr, *pYl = nullptr;
    cudaGetSymbolAddress(&pQh, g_Qth);
    cudaGetSymbolAddress(&pQl, g_Qtl);
    cudaGetSymbolAddress(&pYh, g_Yth);
    cudaGetSymbolAddress(&pYl, g_Ytl);

    cudaFuncSetAttribute(gru_persist,
                         cudaFuncAttributeMaxDynamicSharedMemorySize, GRU_SMEM);
    cudaFuncSetAttribute(ay_mma,
                         cudaFuncAttributeMaxDynamicSharedMemorySize, SMEM_BYTES);

    // 1. Evolve Q over 16 steps (32 persistent blocks; gate-fold inline)
    gru_persist<<<GRU_NB, 256, GRU_SMEM>>>(Q0, Wz, Uz, Wr, Ur, Wh, Uh);

    // 2. Y_t = X_t @ Q_t (static-smem tensor kernel) -> Y^T bf16 hi/lo
    xq_mma<<<dim3(NNODES / 128, TSTEPS), 128>>>(
        X, (const unsigned short*)pQh, (const unsigned short*)pQl,
        (unsigned short*)pYh, (unsigned short*)pYl);

    // 3. out_t = relu(A_t @ Y_t) (cp.async, 8 warps)
    ay_mma<<<dim3(NNODES / 128, TSTEPS), 256, SMEM_BYTES>>>(
        A, (const unsigned short*)pYh, (const unsigned short*)pYl, out);
}